// round 4
// baseline (speedup 1.0000x reference)
#include <cuda_runtime.h>
#include <cuda_bf16.h>
#include <math.h>

#define BB 128
#define TT 256
#define HH 768
#define KK 64

typedef unsigned long long u64t;

__device__ float g_emis[BB * TT * KK];   // emissions scratch, 8 MB

// ---- packed f32x2 helpers ------------------------------------------------
__device__ __forceinline__ u64t ffma2(u64t a, u64t b, u64t c) {
    u64t d;
    asm("fma.rn.f32x2 %0, %1, %2, %3;" : "=l"(d) : "l"(a), "l"(b), "l"(c));
    return d;
}
__device__ __forceinline__ u64t pack2(float lo, float hi) {
    u64t d;
    unsigned a = __float_as_uint(lo), b = __float_as_uint(hi);
    asm("mov.b64 %0, {%1, %2};" : "=l"(d) : "r"(a), "r"(b));
    return d;
}
__device__ __forceinline__ void unpack2(u64t v, float* lo, float* hi) {
    unsigned a, b;
    asm("mov.b64 {%0, %1}, %2;" : "=r"(a), "=r"(b) : "l"(v));
    *lo = __uint_as_float(a);
    *hi = __uint_as_float(b);
}

// ---------------------------------------------------------------------------
// Kernel 1: emissions = hidden @ W + b (unchanged; ~90% of FFMA2 pacing floor)
// ---------------------------------------------------------------------------
__global__ __launch_bounds__(256) void gemm_emis_kernel(
    const float* __restrict__ A,
    const float* __restrict__ Wm,
    const float* __restrict__ bias)
{
    __shared__ float As[16][132];
    __shared__ float Bs[16][64];

    const int tid = threadIdx.x;
    const int m0 = blockIdx.x * 128;
    const int ty = tid >> 4;
    const int tx = tid & 15;

    u64t acc2[4][4];
#pragma unroll
    for (int rp = 0; rp < 4; rp++)
#pragma unroll
        for (int c = 0; c < 4; c++) acc2[rp][c] = 0ull;

    const int arow0 = (tid) >> 2,       ac40 = (tid) & 3;
    const int arow1 = (tid + 256) >> 2, ac41 = (tid + 256) & 3;
    const int brow = tid >> 4, bc4 = tid & 15;

    float4 aReg0 = *(const float4*)&A[(size_t)(m0 + arow0) * HH + ac40 * 4];
    float4 aReg1 = *(const float4*)&A[(size_t)(m0 + arow1) * HH + ac41 * 4];
    float4 bReg  = *(const float4*)&Wm[(size_t)(brow) * KK + bc4 * 4];

    for (int kt = 0; kt < HH; kt += 16) {
        As[ac40 * 4 + 0][arow0] = aReg0.x;
        As[ac40 * 4 + 1][arow0] = aReg0.y;
        As[ac40 * 4 + 2][arow0] = aReg0.z;
        As[ac40 * 4 + 3][arow0] = aReg0.w;
        As[ac41 * 4 + 0][arow1] = aReg1.x;
        As[ac41 * 4 + 1][arow1] = aReg1.y;
        As[ac41 * 4 + 2][arow1] = aReg1.z;
        As[ac41 * 4 + 3][arow1] = aReg1.w;
        *(float4*)&Bs[brow][bc4 * 4] = bReg;
        __syncthreads();

        if (kt + 16 < HH) {
            aReg0 = *(const float4*)&A[(size_t)(m0 + arow0) * HH + kt + 16 + ac40 * 4];
            aReg1 = *(const float4*)&A[(size_t)(m0 + arow1) * HH + kt + 16 + ac41 * 4];
            bReg  = *(const float4*)&Wm[(size_t)(kt + 16 + brow) * KK + bc4 * 4];
        }

#pragma unroll
        for (int kk = 0; kk < 16; kk++) {
            const u64t* ap = (const u64t*)&As[kk][ty * 8];
            u64t a2[4];
#pragma unroll
            for (int rp = 0; rp < 4; rp++) a2[rp] = ap[rp];
            float4 bv = *(const float4*)&Bs[kk][tx * 4];
            u64t bd[4];
            bd[0] = pack2(bv.x, bv.x);
            bd[1] = pack2(bv.y, bv.y);
            bd[2] = pack2(bv.z, bv.z);
            bd[3] = pack2(bv.w, bv.w);
#pragma unroll
            for (int rp = 0; rp < 4; rp++)
#pragma unroll
                for (int c = 0; c < 4; c++)
                    acc2[rp][c] = ffma2(a2[rp], bd[c], acc2[rp][c]);
        }
        __syncthreads();
    }

    float4 bb = *(const float4*)&bias[tx * 4];
    const float bbv[4] = {bb.x, bb.y, bb.z, bb.w};
#pragma unroll
    for (int rp = 0; rp < 4; rp++) {
        float o0[4], o1[4];
#pragma unroll
        for (int c = 0; c < 4; c++) {
            float lo, hi;
            unpack2(acc2[rp][c], &lo, &hi);
            o0[c] = lo + bbv[c];
            o1[c] = hi + bbv[c];
        }
        int row = m0 + ty * 8 + 2 * rp;
        *(float4*)&g_emis[(size_t)row * KK + tx * 4]       = make_float4(o0[0], o0[1], o0[2], o0[3]);
        *(float4*)&g_emis[(size_t)(row + 1) * KK + tx * 4] = make_float4(o1[0], o1[1], o1[2], o1[3]);
    }
}

// ---------------------------------------------------------------------------
// Kernel 2: CRF. grid=256. Blocks [0,128): Viterbi (256 thr). Blocks
// [128,256): forward log-norm + seq_score (64 thr active, named barrier).
// Roles fully independent -> two small blocks co-reside per SM.
// ---------------------------------------------------------------------------
__global__ __launch_bounds__(256) void crf_kernel(
    const int* __restrict__ masks,
    const int* __restrict__ target,
    const float* __restrict__ trans_g,
    float* __restrict__ out_dec,
    float* __restrict__ out_ll)
{
    __shared__ __align__(16) float s_buf[2][64];   // vit: v ; fwd: P
    __shared__ float s_red[8];
    __shared__ int s_len;
    __shared__ int s_path[TT];
    __shared__ unsigned char s_bp[(TT - 1) * KK];

    const int tid = threadIdx.x;
    const bool isVit = (blockIdx.x < BB);
    const int b = isVit ? blockIdx.x : (blockIdx.x - BB);
    const float* emisb = &g_emis[(size_t)b * TT * KK];

    if (isVit) {
        // ================= VITERBI BLOCK: 256 threads, 4 per state ==========
        if (tid < 32) {
            int acc = 0;
#pragma unroll
            for (int i = 0; i < 8; i++) acc += masks[b * TT + tid + 32 * i];
#pragma unroll
            for (int o = 16; o; o >>= 1) acc += __shfl_xor_sync(0xFFFFFFFFu, acc, o);
            if (tid == 0) s_len = acc;
        }

        const int j = tid >> 2;      // state 0..63
        const int q = tid & 3;       // quarter 0..3
        const int k0 = q * 16;

        float Tcol[16];
#pragma unroll
        for (int kk = 0; kk < 16; kk++)
            Tcol[kk] = trans_g[(k0 + kk) * KK + j];

        float e0 = emisb[j];
        float eA = emisb[KK + j];
        float eB = emisb[2 * KK + j];
        float prevV = e0;
        if (q == 0) s_buf[0][j] = e0;
        __syncthreads();
        const int len = s_len;
        int buf = 0;

        for (int t = 1; t < TT; t++) {
            float eC = (t + 2 < TT) ? emisb[(size_t)(t + 2) * KK + j] : 0.f;

            const float4* V4 = (const float4*)&s_buf[buf][k0];
            float4 v0 = V4[0], v1 = V4[1], v2 = V4[2], v3 = V4[3];
            float a[16];
            a[0]  = v0.x + Tcol[0];  a[1]  = v0.y + Tcol[1];
            a[2]  = v0.z + Tcol[2];  a[3]  = v0.w + Tcol[3];
            a[4]  = v1.x + Tcol[4];  a[5]  = v1.y + Tcol[5];
            a[6]  = v1.z + Tcol[6];  a[7]  = v1.w + Tcol[7];
            a[8]  = v2.x + Tcol[8];  a[9]  = v2.y + Tcol[9];
            a[10] = v2.z + Tcol[10]; a[11] = v2.w + Tcol[11];
            a[12] = v3.x + Tcol[12]; a[13] = v3.y + Tcol[13];
            a[14] = v3.z + Tcol[14]; a[15] = v3.w + Tcol[15];

            float pv[8];
            int pi[8];
#pragma unroll
            for (int m = 0; m < 8; m++) {
                bool g = a[2 * m + 1] > a[2 * m];      // strict: lower k wins ties
                pv[m] = g ? a[2 * m + 1] : a[2 * m];
                pi[m] = k0 + 2 * m + (g ? 1 : 0);
            }
#pragma unroll
            for (int s = 1; s < 8; s <<= 1) {
#pragma unroll
                for (int m = 0; m < 8; m += 2 * s) {
                    bool g = pv[m + s] > pv[m];
                    pv[m] = g ? pv[m + s] : pv[m];
                    pi[m] = g ? pi[m + s] : pi[m];
                }
            }
            float bv = pv[0];
            int   ba = pi[0];

            // tie-aware cross-thread combine (exact first-max semantics)
            float ov = __shfl_xor_sync(0xFFFFFFFFu, bv, 1);
            int   oa = __shfl_xor_sync(0xFFFFFFFFu, ba, 1);
            if (ov > bv || (ov == bv && oa < ba)) { bv = ov; ba = oa; }
            ov = __shfl_xor_sync(0xFFFFFFFFu, bv, 2);
            oa = __shfl_xor_sync(0xFFFFFFFFu, ba, 2);
            if (ov > bv || (ov == bv && oa < ba)) { bv = ov; ba = oa; }

            if (q == 0) {
                int bp;
                if (t < len) { prevV = bv + eA; bp = ba; }
                else         { bp = j; }
                s_buf[buf ^ 1][j] = prevV;
                s_bp[(t - 1) * KK + j] = (unsigned char)bp;
            }
            eA = eB;
            eB = eC;
            __syncthreads();
            buf ^= 1;
        }

        if (tid == 0) {
            float bvv = s_buf[buf][0];
            int tg = 0;
#pragma unroll
            for (int k = 1; k < KK; k++)
                if (s_buf[buf][k] > bvv) { bvv = s_buf[buf][k]; tg = k; }
            s_path[TT - 1] = tg;
            for (int t = TT - 1; t >= 1; t--) {
                tg = s_bp[(t - 1) * KK + tg];
                s_path[t - 1] = tg;
            }
        }
        __syncthreads();
        out_dec[(size_t)b * TT + tid] = (float)((tid < len) ? s_path[tid] : 0);

    } else {
        // ================= FORWARD BLOCK: 64 threads (2 warps) ==============
        if (tid >= 64) return;

        if (tid < 32) {
            int acc = 0;
#pragma unroll
            for (int i = 0; i < 8; i++) acc += masks[b * TT + tid + 32 * i];
#pragma unroll
            for (int o = 16; o; o >>= 1) acc += __shfl_xor_sync(0xFFFFFFFFu, acc, o);
            if (tid == 0) s_len = acc;
        }

        const int j = tid;
        u64t E2[32];
#pragma unroll
        for (int m = 0; m < 32; m++) {
            float t0 = trans_g[(2 * m) * KK + j];
            float t1 = trans_g[(2 * m + 1) * KK + j];
            E2[m] = pack2(expf(t0), expf(t1));
        }

        float e0 = emisb[j];
        float eA = emisb[KK + j];
        float eB = emisb[2 * KK + j];
        float prevP = __expf(e0);
        int iexp = 0;
        s_buf[0][j] = prevP;
        asm volatile("bar.sync 1, 64;" ::: "memory");
        const int len = s_len;
        int buf = 0;

        for (int t = 1; t < TT; t++) {
            float eC = (t + 2 < TT) ? emisb[(size_t)(t + 2) * KK + j] : 0.f;

            float p0 = s_buf[buf][0];
            const u64t* P2 = (const u64t*)&s_buf[buf][0];
            u64t s0 = 0ull, s1 = 0ull, s2 = 0ull, s3 = 0ull;
#pragma unroll
            for (int m = 0; m < 8; m++) {
                s0 = ffma2(P2[4 * m + 0], E2[4 * m + 0], s0);
                s1 = ffma2(P2[4 * m + 1], E2[4 * m + 1], s1);
                s2 = ffma2(P2[4 * m + 2], E2[4 * m + 2], s2);
                s3 = ffma2(P2[4 * m + 3], E2[4 * m + 3], s3);
            }
            float l0, h0, l1, h1, l2, h2, l3, h3;
            unpack2(s0, &l0, &h0);
            unpack2(s1, &l1, &h1);
            unpack2(s2, &l2, &h2);
            unpack2(s3, &l3, &h3);
            float S = ((l0 + h0) + (l1 + h1)) + ((l2 + h2) + (l3 + h3));

            // exact power-of-2 rescale by p0's exponent
            int e0i = (int)(__float_as_uint(p0) >> 23);
            float scale = __uint_as_float((unsigned)(254 - e0i) << 23);
            if (t < len) {
                prevP = S * scale * __expf(eA);
                iexp += e0i - 127;
            }
            s_buf[buf ^ 1][j] = prevP;
            eA = eB;
            eB = eC;
            asm volatile("bar.sync 1, 64;" ::: "memory");
            buf ^= 1;
        }

        // log_norm: sum final P across 64 threads
        float sp = prevP;
#pragma unroll
        for (int o = 16; o; o >>= 1) sp += __shfl_xor_sync(0xFFFFFFFFu, sp, o);
        if ((tid & 31) == 0) s_red[tid >> 5] = sp;

        // seq_score partials: 4 t's per thread
        float uacc = 0.f;
#pragma unroll
        for (int i = 0; i < 4; i++) {
            int tt = tid + 64 * i;
            if (tt < len) {
                int tg = target[b * TT + tt];
                uacc += emisb[(size_t)tt * KK + tg];
                if (tt >= 1) uacc += trans_g[target[b * TT + tt - 1] * KK + tg];
            }
        }
#pragma unroll
        for (int o = 16; o; o >>= 1) uacc += __shfl_xor_sync(0xFFFFFFFFu, uacc, o);
        if ((tid & 31) == 0) s_red[2 + (tid >> 5)] = uacc;
        asm volatile("bar.sync 1, 64;" ::: "memory");

        if (tid == 0) {
            float sumP = s_red[0] + s_red[1];
            float score = s_red[2] + s_red[3];
            const float LN2 = 0.69314718055994531f;
            out_ll[b] = score - ((float)iexp * LN2 + logf(sumP));
        }
    }
}

// ---------------------------------------------------------------------------
extern "C" void kernel_launch(void* const* d_in, const int* in_sizes, int n_in,
                              void* d_out, int out_size) {
    const float* hidden = (const float*)d_in[0];
    const int*   masks  = (const int*)d_in[1];
    const int*   target = (const int*)d_in[2];
    const float* Wm     = (const float*)d_in[3];
    const float* bias   = (const float*)d_in[4];
    const float* trans  = (const float*)d_in[5];
    float* out = (float*)d_out;

    gemm_emis_kernel<<<BB * TT / 128, 256>>>(hidden, Wm, bias);
    crf_kernel<<<2 * BB, 256>>>(masks, target, trans, out, out + (size_t)BB * TT);
}